// round 11
// baseline (speedup 1.0000x reference)
#include <cuda_runtime.h>

#define NBINS   256
#define SUBBINS 4096
#define APAR    0.07689350249903885f  // (1/255)^2 / (2*0.01^2)
#define GRATIO  0.85745463520f        // exp(-2*APAR)
#define WSINT   6.3919026f            // sqrt(pi/APAR): interior weight sum
#define FEPS    1e-10f
#define NB      4
#define HW      262144
#define NVEC    (HW / 4)
#define GRID    296                   // 2 CTAs per SM
#define GPB     74                    // blocks per batch
#define NT      512
#define TAPS    27                    // +-13 bins (table build)
#define CTAPS   448                   // conv taps (+-14 bins of sub-bins)
#define TBLN    2048                  // g-table points (1/8 bin)
// smem float offsets
#define SM_GTAB 0                     // gtab 2048 (aliases shu u32[4096] in P1)
#define SM_CDP  2048                  // cdp 288
#define SM_SM2  4096                  // sm2 float2[4096] -> floats [4096,12288)
#define SM_WT   12288                 // wtab 448
#define SM_WD   12736                 // wdtab 448
#define SM_SCN  13184                 // scn 256
#define SMEMB   ((13184 + 256) * 4)   // 53760 B

// persistent scratch (zero-init at load; invariants restored in-kernel)
__device__ unsigned long long g_comb[NB * SUBBINS];   // natural sub-bin order
__device__ float              g_cdfn[NB * NBINS];
__device__ unsigned int       g_bar;
__device__ unsigned int       g_epoch;

// transposed smem slot for conflict spreading in P1
__device__ __forceinline__ int sub_idx(int s) { return ((s & 15) << 8) | (s >> 4); }

__device__ __forceinline__ void gbar(unsigned target) {
    __syncthreads();
    if (threadIdx.x == 0) {
        __threadfence();
        atomicAdd(&g_bar, 1u);
        unsigned v;
        do {
            asm volatile("ld.global.acquire.gpu.b32 %0, [%1];"
                         : "=r"(v) : "l"(&g_bar) : "memory");
        } while (v < target);
    }
    __syncthreads();
}

__global__ __launch_bounds__(NT, 2) void fused(const float* __restrict__ x,
                                               float* __restrict__ out) {
    extern __shared__ __align__(16) float smf[];
    float*    gtab = smf + SM_GTAB;
    float*    cdp  = smf + SM_CDP;
    float2*   sm2  = (float2*)(smf + SM_SM2);
    float*    wtab = smf + SM_WT;
    float*    wdtab= smf + SM_WD;
    float*    scn  = smf + SM_SCN;
    unsigned* shu  = (unsigned*)smf;          // P1 alias over gtab/cdp region

    const int tid   = threadIdx.x;
    const int bid   = blockIdx.x;
    const int lane  = tid & 31;
    const int warp  = tid >> 5;
    const int batch = bid / GPB;
    const int sub   = bid % GPB;

    __shared__ unsigned s_ep;
    if (tid == 0) s_ep = g_epoch;

    // ---- P0: conv tap tables (data-independent) ----
    for (int i = tid; i < 2 * CTAPS; i += NT) {
        int  k = (i >= CTAPS) ? i - CTAPS : i;
        float d = ((float)k - 224.0f + 0.5f) * 0.0625f;
        float w = __expf(-APAR * d * d);
        if (i < CTAPS) wtab[k] = w;
        else           wdtab[k] = -2.0f * APAR * d * w;
    }

    // ---- P1: packed sub-bin histogram (smem atomics, pre-aggregated) ----
    for (int i = tid; i < SUBBINS; i += NT) shu[i] = 0u;
    __syncthreads();
    const unsigned ep = s_ep;

    const float4* xb = (const float4*)(x + (size_t)batch * HW);
    for (int i = sub * NT + tid; i < NVEC; i += GPB * NT) {
        float4 v = xb[i];
        float vals[4] = {v.x, v.y, v.z, v.w};
        #pragma unroll
        for (int q = 0; q < 4; q++) {
            float t = vals[q] * 4080.0f;            // u*16
            int s = min((int)t, SUBBINS - 1);
            float d16 = t - (float)s - 0.5f;        // 16*dev in [-0.5,0.5]
            unsigned val = 0x100000u + (unsigned)fmaf(d16, 1024.0f, 8192.0f);
            atomicAdd(&shu[sub_idx(s)], val);
        }
    }
    __syncthreads();
    for (int i = tid; i < SUBBINS; i += NT) {
        unsigned v = shu[i];
        if (v) {
            int s = ((i & 255) << 4) | (i >> 8);    // inverse of sub_idx
            unsigned long long w = ((unsigned long long)(v >> 20) << 48)
                                 | (unsigned long long)(v & 0xFFFFFu);
            atomicAdd(&g_comb[batch * SUBBINS + s], w);
        }
    }
    gbar(ep + GRID);

    // ---- P2': blocks 0..3: decode+zero g_comb, conv, scan, cdfn ----
    if (bid < NB) {
        unsigned long long* cb = g_comb + bid * SUBBINS;
        for (int i = tid; i < SUBBINS; i += NT) {
            unsigned long long t = __ldcg(&cb[i]);
            float cnt = (float)(unsigned)(t >> 48);
            long long df = (long long)(t & 0xFFFFFFFFFFFFull)
                         - ((long long)(t >> 48) << 13);
            sm2[i] = make_float2(cnt, (float)df * 6.1035156e-5f);  // 2^-14
            cb[i] = 0ull;                            // restore for next replay
        }
        __syncthreads();

        // warp w computes bins [16w, 16w+16), lane-strided taps (conflict-free)
        #pragma unroll 1
        for (int bb = 0; bb < 16; bb++) {
            int j = warp * 16 + bb;
            int sbase = 16 * j - 224 + lane;
            float h = 0.f;
            #pragma unroll
            for (int k = 0; k < 14; k++) {
                int s = sbase + 32 * k;
                if ((unsigned)s < (unsigned)SUBBINS) {
                    float2 cd = sm2[s];
                    int idx = lane + 32 * k;
                    h = fmaf(cd.x, wtab[idx], h);
                    h = fmaf(cd.y, wdtab[idx], h);
                }
            }
            #pragma unroll
            for (int o = 16; o; o >>= 1) h += __shfl_xor_sync(0xFFFFFFFFu, h, o);
            if (lane == 0) scn[j] = h;
        }
        __syncthreads();

        // inclusive scan + normalize
        for (int off = 1; off < NBINS; off <<= 1) {
            float add = (tid < NBINS && tid >= off) ? scn[tid - off] : 0.f;
            __syncthreads();
            if (tid < NBINS) scn[tid] += add;
            __syncthreads();
        }
        if (tid < NBINS) {
            float S = scn[NBINS - 1];
            float invS = 1.0f / (S + FEPS);
            float c0 = scn[0] * invS;
            g_cdfn[bid * NBINS + tid] = (scn[tid] * invS - c0) / (1.0f - c0 + FEPS);
        }
    }
    gbar(ep + 2 * GRID);

    // ---- P4: build this batch's 2048-pt g-table in smem ----
    {
        const float* cdfn = g_cdfn + (batch << 8);
        for (int i = tid; i < 288; i += NT) {
            int j = i - 13;
            cdp[i] = ((unsigned)j < 256u) ? __ldcg(cdfn + j) : 0.f;
        }
        __syncthreads();
        #pragma unroll
        for (int it = 0; it < TBLN / NT; it++) {
            int   m  = it * NT + tid;
            int   fl = m >> 3;
            float d0 = (float)(m & 7) * 0.125f + 13.0f;
            float w  = __expf(-APAR * d0 * d0);
            float f  = __expf(fmaf(2.0f * APAR, d0, -APAR));
            const float w0 = w, f0 = f;
            float acc = 0.f;
            #pragma unroll
            for (int k = 0; k < TAPS; k++) {
                acc = fmaf(w, cdp[fl + k], acc);    // zero-padded: no predicate
                w *= f;
                f *= GRATIO;
            }
            float ws;
            if (fl >= 13 && fl <= 242) {
                ws = WSINT;                          // interior: analytic constant
            } else {
                ws = 0.f; w = w0; f = f0;
                #pragma unroll
                for (int k = 0; k < TAPS; k++) {
                    int jj = fl - 13 + k;
                    ws += ((unsigned)jj < 256u) ? w : 0.f;
                    w *= f;
                    f *= GRATIO;
                }
            }
            gtab[m] = __fdividef(acc, ws + FEPS);
        }
        __syncthreads();
    }

    // ---- P5: per-pixel linear interpolation ----
    {
        float4* ob = (float4*)(out + (size_t)batch * HW);
        for (int i = sub * NT + tid; i < NVEC; i += GPB * NT) {
            float4 v = xb[i];
            float4 o;
            float t; int ix; float fr, lo;
            t = v.x * 2040.0f; ix = (int)t; fr = t - (float)ix;
            lo = gtab[ix]; o.x = fmaf(fr, gtab[ix + 1] - lo, lo);
            t = v.y * 2040.0f; ix = (int)t; fr = t - (float)ix;
            lo = gtab[ix]; o.y = fmaf(fr, gtab[ix + 1] - lo, lo);
            t = v.z * 2040.0f; ix = (int)t; fr = t - (float)ix;
            lo = gtab[ix]; o.z = fmaf(fr, gtab[ix + 1] - lo, lo);
            t = v.w * 2040.0f; ix = (int)t; fr = t - (float)ix;
            lo = gtab[ix]; o.w = fmaf(fr, gtab[ix + 1] - lo, lo);
            ob[i] = o;
        }
    }

    if (bid == 0 && tid == 0) g_epoch = ep + 2 * GRID;
}

extern "C" void kernel_launch(void* const* d_in, const int* in_sizes, int n_in,
                              void* d_out, int out_size) {
    const float* x = (const float*)d_in[0];
    float* out = (float*)d_out;
    cudaFuncSetAttribute(fused, cudaFuncAttributeMaxDynamicSharedMemorySize, SMEMB);
    fused<<<GRID, NT, SMEMB>>>(x, out);
}

// round 12
// speedup vs baseline: 1.2092x; 1.2092x over previous
#include <cuda_runtime.h>

#define NBINS   256
#define SUBBINS 4096
#define APAR    0.07689350249903885f  // (1/255)^2 / (2*0.01^2)
#define GRATIO  0.85745463520f        // exp(-2*APAR)
#define WSINT   6.3919026f            // sqrt(pi/APAR): interior weight sum
#define FEPS    1e-10f
#define NB      4
#define HW      262144
#define NVEC    (HW / 4)
#define GRID    148                   // 1 CTA per SM (2/SM measured worse: R11)
#define GPB     37                    // blocks per batch
#define NT      512
#define TAPS    27                    // +-13 bins (table build)
#define CTAPS   448                   // conv taps (+-14 bins of sub-bins)
#define TBLN    2048                  // g-table points (1/8 bin)
// smem float offsets
#define SM_GTAB 0                     // gtab 2048 (aliases shu u32[4096] in P1)
#define SM_CDP  2048                  // cdp 288
#define SM_SM2  4096                  // sm2 float2[4096] -> floats [4096,12288)
#define SM_WT   12288                 // wtab 448
#define SM_WD   12736                 // wdtab 448
#define SM_SCN  13184                 // scn 256
#define SMEMB   ((13184 + 256) * 4)   // 53760 B

// persistent scratch (zero-init at load; invariants restored in-kernel)
__device__ unsigned long long g_comb[NB * SUBBINS];   // natural sub-bin order
__device__ float              g_cdfn[NB * NBINS];
__device__ unsigned int       g_bar;
__device__ unsigned int       g_epoch;

// transposed smem slot for conflict spreading in P1
__device__ __forceinline__ int sub_idx(int s) { return ((s & 15) << 8) | (s >> 4); }

__device__ __forceinline__ void gbar(unsigned target) {
    __syncthreads();
    if (threadIdx.x == 0) {
        __threadfence();
        atomicAdd(&g_bar, 1u);
        unsigned v;
        do {
            asm volatile("ld.global.acquire.gpu.b32 %0, [%1];"
                         : "=r"(v) : "l"(&g_bar) : "memory");
        } while (v < target);
    }
    __syncthreads();
}

__global__ __launch_bounds__(NT, 1) void fused(const float* __restrict__ x,
                                               float* __restrict__ out) {
    extern __shared__ __align__(16) float smf[];
    float*    gtab = smf + SM_GTAB;
    float*    cdp  = smf + SM_CDP;
    float2*   sm2  = (float2*)(smf + SM_SM2);
    float*    wtab = smf + SM_WT;
    float*    wdtab= smf + SM_WD;
    float*    scn  = smf + SM_SCN;
    unsigned* shu  = (unsigned*)smf;          // P1 alias over gtab/cdp region

    const int tid   = threadIdx.x;
    const int bid   = blockIdx.x;
    const int lane  = tid & 31;
    const int warp  = tid >> 5;
    const int batch = bid / GPB;
    const int sub   = bid % GPB;

    __shared__ unsigned s_ep;
    if (tid == 0) s_ep = g_epoch;

    // ---- P0: conv tap tables (data-independent; only blocks 0..3 use them) ----
    if (bid < NB) {
        for (int i = tid; i < 2 * CTAPS; i += NT) {
            int  k = (i >= CTAPS) ? i - CTAPS : i;
            float d = ((float)k - 224.0f + 0.5f) * 0.0625f;
            float w = __expf(-APAR * d * d);
            if (i < CTAPS) wtab[k] = w;
            else           wdtab[k] = -2.0f * APAR * d * w;
        }
    }

    // ---- P1: packed sub-bin histogram (smem atomics, pre-aggregated) ----
    for (int i = tid; i < SUBBINS; i += NT) shu[i] = 0u;
    __syncthreads();
    const unsigned ep = s_ep;

    const float4* xb = (const float4*)(x + (size_t)batch * HW);
    for (int i = sub * NT + tid; i < NVEC; i += GPB * NT) {
        float4 v = xb[i];
        float vals[4] = {v.x, v.y, v.z, v.w};
        #pragma unroll
        for (int q = 0; q < 4; q++) {
            float t = vals[q] * 4080.0f;            // u*16
            int s = min((int)t, SUBBINS - 1);
            float d16 = t - (float)s - 0.5f;        // 16*dev in [-0.5,0.5]
            unsigned val = 0x100000u + (unsigned)fmaf(d16, 1024.0f, 8192.0f);
            atomicAdd(&shu[sub_idx(s)], val);
        }
    }
    __syncthreads();
    for (int i = tid; i < SUBBINS; i += NT) {
        unsigned v = shu[i];
        if (v) {
            int s = ((i & 255) << 4) | (i >> 8);    // inverse of sub_idx
            unsigned long long w = ((unsigned long long)(v >> 20) << 48)
                                 | (unsigned long long)(v & 0xFFFFFu);
            atomicAdd(&g_comb[batch * SUBBINS + s], w);
        }
    }
    gbar(ep + GRID);

    // ---- P2': blocks 0..3: decode+zero g_comb, conv, scan, cdfn ----
    if (bid < NB) {
        unsigned long long* cb = g_comb + bid * SUBBINS;
        for (int i = tid; i < SUBBINS; i += NT) {
            unsigned long long t = __ldcg(&cb[i]);
            float cnt = (float)(unsigned)(t >> 48);
            long long df = (long long)(t & 0xFFFFFFFFFFFFull)
                         - ((long long)(t >> 48) << 13);
            sm2[i] = make_float2(cnt, (float)df * 6.1035156e-5f);  // 2^-14
            cb[i] = 0ull;                            // restore for next replay
        }
        __syncthreads();

        // warp w computes bins [16w, 16w+16), lane-strided taps (conflict-free)
        #pragma unroll 1
        for (int bb = 0; bb < 16; bb++) {
            int j = warp * 16 + bb;
            int sbase = 16 * j - 224 + lane;
            float h = 0.f;
            #pragma unroll
            for (int k = 0; k < 14; k++) {
                int s = sbase + 32 * k;
                if ((unsigned)s < (unsigned)SUBBINS) {
                    float2 cd = sm2[s];
                    int idx = lane + 32 * k;
                    h = fmaf(cd.x, wtab[idx], h);
                    h = fmaf(cd.y, wdtab[idx], h);
                }
            }
            #pragma unroll
            for (int o = 16; o; o >>= 1) h += __shfl_xor_sync(0xFFFFFFFFu, h, o);
            if (lane == 0) scn[j] = h;
        }
        __syncthreads();

        // inclusive scan + normalize
        for (int off = 1; off < NBINS; off <<= 1) {
            float add = (tid < NBINS && tid >= off) ? scn[tid - off] : 0.f;
            __syncthreads();
            if (tid < NBINS) scn[tid] += add;
            __syncthreads();
        }
        if (tid < NBINS) {
            float S = scn[NBINS - 1];
            float invS = 1.0f / (S + FEPS);
            float c0 = scn[0] * invS;
            g_cdfn[bid * NBINS + tid] = (scn[tid] * invS - c0) / (1.0f - c0 + FEPS);
        }
    }
    gbar(ep + 2 * GRID);

    // ---- P4: build this batch's 2048-pt g-table in smem ----
    {
        const float* cdfn = g_cdfn + (batch << 8);
        for (int i = tid; i < 288; i += NT) {
            int j = i - 13;
            cdp[i] = ((unsigned)j < 256u) ? __ldcg(cdfn + j) : 0.f;
        }
        __syncthreads();
        #pragma unroll
        for (int it = 0; it < TBLN / NT; it++) {
            int   m  = it * NT + tid;
            int   fl = m >> 3;
            float d0 = (float)(m & 7) * 0.125f + 13.0f;
            float w  = __expf(-APAR * d0 * d0);
            float f  = __expf(fmaf(2.0f * APAR, d0, -APAR));
            const float w0 = w, f0 = f;
            float acc = 0.f;
            #pragma unroll
            for (int k = 0; k < TAPS; k++) {
                acc = fmaf(w, cdp[fl + k], acc);    // zero-padded: no predicate
                w *= f;
                f *= GRATIO;
            }
            float ws;
            if (fl >= 13 && fl <= 242) {
                ws = WSINT;                          // interior: analytic constant
            } else {
                ws = 0.f; w = w0; f = f0;
                #pragma unroll
                for (int k = 0; k < TAPS; k++) {
                    int jj = fl - 13 + k;
                    ws += ((unsigned)jj < 256u) ? w : 0.f;
                    w *= f;
                    f *= GRATIO;
                }
            }
            gtab[m] = __fdividef(acc, ws + FEPS);
        }
        __syncthreads();
    }

    // ---- P5: per-pixel linear interpolation ----
    {
        float4* ob = (float4*)(out + (size_t)batch * HW);
        for (int i = sub * NT + tid; i < NVEC; i += GPB * NT) {
            float4 v = xb[i];
            float4 o;
            float t; int ix; float fr, lo;
            t = v.x * 2040.0f; ix = (int)t; fr = t - (float)ix;
            lo = gtab[ix]; o.x = fmaf(fr, gtab[ix + 1] - lo, lo);
            t = v.y * 2040.0f; ix = (int)t; fr = t - (float)ix;
            lo = gtab[ix]; o.y = fmaf(fr, gtab[ix + 1] - lo, lo);
            t = v.z * 2040.0f; ix = (int)t; fr = t - (float)ix;
            lo = gtab[ix]; o.z = fmaf(fr, gtab[ix + 1] - lo, lo);
            t = v.w * 2040.0f; ix = (int)t; fr = t - (float)ix;
            lo = gtab[ix]; o.w = fmaf(fr, gtab[ix + 1] - lo, lo);
            ob[i] = o;
        }
    }

    if (bid == 0 && tid == 0) g_epoch = ep + 2 * GRID;
}

extern "C" void kernel_launch(void* const* d_in, const int* in_sizes, int n_in,
                              void* d_out, int out_size) {
    const float* x = (const float*)d_in[0];
    float* out = (float*)d_out;
    cudaFuncSetAttribute(fused, cudaFuncAttributeMaxDynamicSharedMemorySize, SMEMB);
    fused<<<GRID, NT, SMEMB>>>(x, out);
}

// round 13
// speedup vs baseline: 1.5165x; 1.2541x over previous
#include <cuda_runtime.h>

#define NBINS   256
#define SUBBINS 4096
#define APAR    0.07689350249903885f  // (1/255)^2 / (2*0.01^2)
#define GRATIO  0.85745463520f        // exp(-2*APAR)
#define WSINT   6.3919026f            // sqrt(pi/APAR): interior weight sum
#define FEPS    1e-10f
#define NB      4
#define HW      262144
#define NVEC    (HW / 4)
#define GRID    148                   // 1 CTA/SM (2/SM regressed: R11)
#define GPB     37                    // blocks per batch
#define NT      512
#define TAPS    27                    // +-13 bins (table build)
#define TBLN    2048                  // g-table points (1/8 bin)
// smem float offsets: shu u32[4096] (P1) aliases [gtab 2048 | cdp 288 | scn 256]
#define SM_GTAB 0
#define SM_CDP  2048
#define SM_SCN  2336
#define SM_GT2  4096                  // gt2 float2[2048] -> floats [4096,8192)
#define SMEMB   (8192 * 4)            // 32 KB

// persistent scratch (zero-init at load; invariants restored in-kernel)
__device__ unsigned long long g_comb[NB * SUBBINS];   // natural sub-bin order
__device__ float              g_hist[NB * NBINS];
__device__ float              g_cdfn[NB * NBINS];
__device__ unsigned int       g_bar;
__device__ unsigned int       g_epoch;

// transposed smem slot for conflict spreading in P1
__device__ __forceinline__ int sub_idx(int s) { return ((s & 15) << 8) | (s >> 4); }

__device__ __forceinline__ void gbar(unsigned target) {
    __syncthreads();
    if (threadIdx.x == 0) {
        __threadfence();
        atomicAdd(&g_bar, 1u);
        unsigned v;
        do {
            asm volatile("ld.global.acquire.gpu.b32 %0, [%1];"
                         : "=r"(v) : "l"(&g_bar) : "memory");
        } while (v < target);
    }
    __syncthreads();
}

__global__ __launch_bounds__(NT, 1) void fused(const float* __restrict__ x,
                                               float* __restrict__ out) {
    extern __shared__ __align__(16) float smf[];
    float*    gtab = smf + SM_GTAB;
    float*    cdp  = smf + SM_CDP;           // zero-padded cdfn
    float*    scn  = smf + SM_SCN;
    float2*   gt2  = (float2*)(smf + SM_GT2);
    unsigned* shu  = (unsigned*)smf;         // P1 alias (dead before P4)

    const int tid   = threadIdx.x;
    const int bid   = blockIdx.x;
    const int lane  = tid & 31;
    const int warp  = tid >> 5;
    const int batch = bid / GPB;
    const int sub   = bid % GPB;

    __shared__ unsigned s_ep;
    if (tid == 0) s_ep = g_epoch;

    // ---- P1: packed sub-bin histogram (smem atomics, pre-aggregated) ----
    for (int i = tid; i < SUBBINS; i += NT) shu[i] = 0u;
    __syncthreads();
    const unsigned ep = s_ep;

    const float4* xb = (const float4*)(x + (size_t)batch * HW);
    for (int i = sub * NT + tid; i < NVEC; i += GPB * NT) {
        float4 v = xb[i];
        float vals[4] = {v.x, v.y, v.z, v.w};
        #pragma unroll
        for (int q = 0; q < 4; q++) {
            // p = floor(v*4080*1024); s = p>>10; field = 7680 + (p & 1023)
            // identical quantization to floor(frac*1024)+7680 bias scheme
            float tk = vals[q] * 4177920.0f;
            unsigned p = (unsigned)tk;
            unsigned s = min(p >> 10, (unsigned)(SUBBINS - 1));
            unsigned val = 0x101E00u + (p & 1023u);
            atomicAdd(&shu[sub_idx(s)], val);
        }
    }
    __syncthreads();
    for (int i = tid; i < SUBBINS; i += NT) {
        unsigned v = shu[i];
        if (v) {
            int s = ((i & 255) << 4) | (i >> 8);    // inverse of sub_idx
            unsigned long long w = ((unsigned long long)(v >> 20) << 48)
                                 | (unsigned long long)(v & 0xFFFFFu);
            atomicAdd(&g_comb[batch * SUBBINS + s], w);
        }
    }
    gbar(ep + GRID);

    // ---- P2: conv -> hist (one warp per bin, distributed over 64 blocks) ----
    {
        int wg = bid * 16 + warp;
        if (wg < NB * NBINS) {
            int b = wg >> 8, j = wg & 255;
            float h = 0.f;
            int sbase = 16 * j - 224 + lane;
            #pragma unroll
            for (int t = 0; t < 14; t++) {
                int s = sbase + t * 32;
                if ((unsigned)s < (unsigned)SUBBINS) {
                    unsigned long long cw = __ldcg(&g_comb[b * SUBBINS + s]);
                    float cnt = (float)(unsigned)(cw >> 48);
                    long long df = (long long)(cw & 0xFFFFFFFFFFFFull)
                                 - ((long long)(cw >> 48) << 13);
                    float dev = (float)df * 6.1035156e-5f;   // 2^-14
                    float d = ((float)s + 0.5f) * 0.0625f - (float)j;
                    float w = __expf(-APAR * d * d);
                    h = fmaf(cnt, w, h);
                    h = fmaf(dev, -2.0f * APAR * d * w, h);
                }
            }
            #pragma unroll
            for (int o = 16; o; o >>= 1) h += __shfl_xor_sync(0xFFFFFFFFu, h, o);
            if (lane == 0) g_hist[wg] = h;
        }
    }
    gbar(ep + 2 * GRID);

    // ---- P3: scan + cdf normalize (blocks 0..3); others re-zero g_comb ----
    if (bid < NB) {
        if (tid < NBINS) scn[tid] = __ldcg(&g_hist[bid * NBINS + tid]);
        __syncthreads();
        for (int off = 1; off < NBINS; off <<= 1) {
            float add = (tid < NBINS && tid >= off) ? scn[tid - off] : 0.f;
            __syncthreads();
            if (tid < NBINS) scn[tid] += add;
            __syncthreads();
        }
        if (tid < NBINS) {
            float S = scn[NBINS - 1];
            float invS = 1.0f / (S + FEPS);
            float c0 = scn[0] * invS;
            g_cdfn[bid * NBINS + tid] = (scn[tid] * invS - c0) / (1.0f - c0 + FEPS);
        }
    } else {
        int rb = bid - NB;
        for (int p = rb * NT + tid; p < NB * SUBBINS; p += (GRID - NB) * NT)
            g_comb[p] = 0ull;
    }
    gbar(ep + 3 * GRID);

    // ---- P4: build 2048-pt g-table, then (value,delta) pairs ----
    {
        const float* cdfn = g_cdfn + (batch << 8);
        for (int i = tid; i < 288; i += NT) {
            int j = i - 13;
            cdp[i] = ((unsigned)j < 256u) ? __ldcg(cdfn + j) : 0.f;
        }
        __syncthreads();
        #pragma unroll
        for (int it = 0; it < TBLN / NT; it++) {
            int   m  = it * NT + tid;
            int   fl = m >> 3;
            float d0 = (float)(m & 7) * 0.125f + 13.0f;
            float w  = __expf(-APAR * d0 * d0);
            float f  = __expf(fmaf(2.0f * APAR, d0, -APAR));
            const float w0 = w, f0 = f;
            float acc = 0.f;
            #pragma unroll
            for (int k = 0; k < TAPS; k++) {
                acc = fmaf(w, cdp[fl + k], acc);    // zero-padded: no predicate
                w *= f;
                f *= GRATIO;
            }
            float ws;
            if (fl >= 13 && fl <= 242) {
                ws = WSINT;                          // interior: analytic constant
            } else {
                ws = 0.f; w = w0; f = f0;
                #pragma unroll
                for (int k = 0; k < TAPS; k++) {
                    int jj = fl - 13 + k;
                    ws += ((unsigned)jj < 256u) ? w : 0.f;
                    w *= f;
                    f *= GRATIO;
                }
            }
            gtab[m] = __fdividef(acc, ws + FEPS);
        }
        __syncthreads();
        for (int m = tid; m < TBLN; m += NT) {
            float lo = gtab[m];
            float hi = (m < TBLN - 1) ? gtab[m + 1] : lo;
            gt2[m] = make_float2(lo, hi - lo);
        }
        __syncthreads();
    }

    // ---- P5: per-pixel lerp, one LDS.64 + FMA per pixel ----
    {
        float4* ob = (float4*)(out + (size_t)batch * HW);
        for (int i = sub * NT + tid; i < NVEC; i += GPB * NT) {
            float4 v = xb[i];
            float4 o;
            float t; int ix; float fr; float2 gd;
            t = v.x * 2040.0f; ix = (int)t; fr = t - (float)ix;
            gd = gt2[ix]; o.x = fmaf(fr, gd.y, gd.x);
            t = v.y * 2040.0f; ix = (int)t; fr = t - (float)ix;
            gd = gt2[ix]; o.y = fmaf(fr, gd.y, gd.x);
            t = v.z * 2040.0f; ix = (int)t; fr = t - (float)ix;
            gd = gt2[ix]; o.z = fmaf(fr, gd.y, gd.x);
            t = v.w * 2040.0f; ix = (int)t; fr = t - (float)ix;
            gd = gt2[ix]; o.w = fmaf(fr, gd.y, gd.x);
            ob[i] = o;
        }
    }

    if (bid == 0 && tid == 0) g_epoch = ep + 3 * GRID;
}

extern "C" void kernel_launch(void* const* d_in, const int* in_sizes, int n_in,
                              void* d_out, int out_size) {
    const float* x = (const float*)d_in[0];
    float* out = (float*)d_out;
    cudaFuncSetAttribute(fused, cudaFuncAttributeMaxDynamicSharedMemorySize, SMEMB);
    fused<<<GRID, NT, SMEMB>>>(x, out);
}

// round 14
// speedup vs baseline: 1.8649x; 1.2297x over previous
#include <cuda_runtime.h>

#define NBINS   256
#define SUBBINS 4096
#define APAR    0.07689350249903885f  // (1/255)^2 / (2*0.01^2)
#define GRATIO  0.85745463520f        // exp(-2*APAR)
#define WSINT   6.3919026f            // sqrt(pi/APAR): interior weight sum
#define FEPS    1e-10f
#define NB      4
#define HW      262144
#define NVEC    (HW / 4)
#define GRID    148                   // 1 CTA/SM (2/SM regressed: R11)
#define GPB     37                    // blocks per batch
#define NT      512
#define TAPS    27                    // +-13 bins (table build)
#define TBLN    2048                  // g-table points (1/8 bin)
// smem float offsets: shu u32[4096] (P1) aliases [gtab 2048 | cdp 288 | scn 256]
#define SM_GTAB 0
#define SM_CDP  2048
#define SM_SCN  2336
#define SM_GT2  4096                  // gt2 float2[2048] -> floats [4096,8192)
#define SMEMB   (8192 * 4)            // 32 KB

// persistent scratch (zero-init at load; invariants restored in-kernel)
__device__ unsigned long long g_comb[NB * SUBBINS];   // natural sub-bin order
__device__ float              g_hist[NB * NBINS];
__device__ unsigned int       g_bar;
__device__ unsigned int       g_epoch;

__device__ __forceinline__ void gbar(unsigned target) {
    __syncthreads();
    if (threadIdx.x == 0) {
        __threadfence();
        atomicAdd(&g_bar, 1u);
        unsigned v;
        do {
            asm volatile("ld.global.acquire.gpu.b32 %0, [%1];"
                         : "=r"(v) : "l"(&g_bar) : "memory");
        } while (v < target);
    }
    __syncthreads();
}

__global__ __launch_bounds__(NT, 1) void fused(const float* __restrict__ x,
                                               float* __restrict__ out) {
    extern __shared__ __align__(16) float smf[];
    float*    gtab = smf + SM_GTAB;
    float*    cdp  = smf + SM_CDP;           // zero-padded cdfn
    float*    scn  = smf + SM_SCN;
    float2*   gt2  = (float2*)(smf + SM_GT2);
    unsigned* shu  = (unsigned*)smf;         // P1 alias (dead before P4)

    const int tid   = threadIdx.x;
    const int bid   = blockIdx.x;
    const int lane  = tid & 31;
    const int warp  = tid >> 5;
    const int batch = bid / GPB;
    const int sub   = bid % GPB;

    __shared__ unsigned s_ep;
    if (tid == 0) s_ep = g_epoch;

    // ---- P1: packed sub-bin histogram (smem atomics, natural order) ----
    for (int i = tid; i < SUBBINS; i += NT) shu[i] = 0u;
    __syncthreads();
    const unsigned ep = s_ep;

    const float4* xb = (const float4*)(x + (size_t)batch * HW);
    for (int i = sub * NT + tid; i < NVEC; i += GPB * NT) {
        float4 v = xb[i];
        float vals[4] = {v.x, v.y, v.z, v.w};
        #pragma unroll
        for (int q = 0; q < 4; q++) {
            // p = floor(v*4080*1024); s = p>>10 (<=4080); field = 7680+(p&1023)
            float tk = vals[q] * 4177920.0f;
            unsigned p = (unsigned)tk;
            atomicAdd(&shu[p >> 10], 0x101E00u + (p & 1023u));
        }
    }
    __syncthreads();
    for (int i = tid; i < SUBBINS; i += NT) {
        unsigned v = shu[i];
        if (v) {
            unsigned long long w = ((unsigned long long)(v >> 20) << 48)
                                 | (unsigned long long)(v & 0xFFFFFu);
            atomicAdd(&g_comb[batch * SUBBINS + i], w);
        }
    }
    gbar(ep + GRID);

    // ---- P2: conv -> hist (one warp per bin, distributed over 64 blocks) ----
    {
        int wg = bid * 16 + warp;
        if (wg < NB * NBINS) {
            int b = wg >> 8, j = wg & 255;
            float h = 0.f;
            int sbase = 16 * j - 224 + lane;
            #pragma unroll
            for (int t = 0; t < 14; t++) {
                int s = sbase + t * 32;
                if ((unsigned)s < (unsigned)SUBBINS) {
                    unsigned long long cw = __ldcg(&g_comb[b * SUBBINS + s]);
                    float cnt = (float)(unsigned)(cw >> 48);
                    long long df = (long long)(cw & 0xFFFFFFFFFFFFull)
                                 - ((long long)(cw >> 48) << 13);
                    float dev = (float)df * 6.1035156e-5f;   // 2^-14
                    float d = ((float)s + 0.5f) * 0.0625f - (float)j;
                    float w = __expf(-APAR * d * d);
                    h = fmaf(cnt, w, h);
                    h = fmaf(dev, -2.0f * APAR * d * w, h);
                }
            }
            #pragma unroll
            for (int o = 16; o; o >>= 1) h += __shfl_xor_sync(0xFFFFFFFFu, h, o);
            if (lane == 0) g_hist[wg] = h;
        }
    }
    gbar(ep + 2 * GRID);

    // ---- P3': every block: zero own g_comb slice; local scan -> cdfn in cdp ----
    {
        // contiguous per-block chunk of g_comb re-zero (conv reads are done)
        const int chunk = (NB * SUBBINS + GRID - 1) / GRID;   // 111
        int base = bid * chunk;
        for (int p = base + tid; p < base + chunk && p < NB * SUBBINS; p += NT)
            g_comb[p] = 0ull;

        if (tid < 288) cdp[tid] = 0.f;       // zero-pad (edges stay 0)
        if (tid < NBINS) scn[tid] = __ldcg(&g_hist[batch * NBINS + tid]);
        __syncthreads();
        for (int off = 1; off < NBINS; off <<= 1) {
            float add = (tid < NBINS && tid >= off) ? scn[tid - off] : 0.f;
            __syncthreads();
            if (tid < NBINS) scn[tid] += add;
            __syncthreads();
        }
        if (tid < NBINS) {
            float S = scn[NBINS - 1];
            float invS = 1.0f / (S + FEPS);
            float c0 = scn[0] * invS;
            cdp[tid + 13] = (scn[tid] * invS - c0) / (1.0f - c0 + FEPS);
        }
        __syncthreads();
    }

    // ---- P4: build 2048-pt g-table, then (value,delta) pairs ----
    {
        #pragma unroll
        for (int it = 0; it < TBLN / NT; it++) {
            int   m  = it * NT + tid;
            int   fl = m >> 3;
            float d0 = (float)(m & 7) * 0.125f + 13.0f;
            float w  = __expf(-APAR * d0 * d0);
            float f  = __expf(fmaf(2.0f * APAR, d0, -APAR));
            const float w0 = w, f0 = f;
            float acc = 0.f;
            #pragma unroll
            for (int k = 0; k < TAPS; k++) {
                acc = fmaf(w, cdp[fl + k], acc);    // zero-padded: no predicate
                w *= f;
                f *= GRATIO;
            }
            float ws;
            if (fl >= 13 && fl <= 242) {
                ws = WSINT;                          // interior: analytic constant
            } else {
                ws = 0.f; w = w0; f = f0;
                #pragma unroll
                for (int k = 0; k < TAPS; k++) {
                    int jj = fl - 13 + k;
                    ws += ((unsigned)jj < 256u) ? w : 0.f;
                    w *= f;
                    f *= GRATIO;
                }
            }
            gtab[m] = __fdividef(acc, ws + FEPS);
        }
        __syncthreads();
        for (int m = tid; m < TBLN; m += NT) {
            float lo = gtab[m];
            float hi = (m < TBLN - 1) ? gtab[m + 1] : lo;
            gt2[m] = make_float2(lo, hi - lo);
        }
        __syncthreads();
    }

    // ---- P5: per-pixel lerp, one LDS.64 + FMA per pixel ----
    {
        float4* ob = (float4*)(out + (size_t)batch * HW);
        for (int i = sub * NT + tid; i < NVEC; i += GPB * NT) {
            float4 v = xb[i];
            float4 o;
            float t; int ix; float fr; float2 gd;
            t = v.x * 2040.0f; ix = (int)t; fr = t - (float)ix;
            gd = gt2[ix]; o.x = fmaf(fr, gd.y, gd.x);
            t = v.y * 2040.0f; ix = (int)t; fr = t - (float)ix;
            gd = gt2[ix]; o.y = fmaf(fr, gd.y, gd.x);
            t = v.z * 2040.0f; ix = (int)t; fr = t - (float)ix;
            gd = gt2[ix]; o.z = fmaf(fr, gd.y, gd.x);
            t = v.w * 2040.0f; ix = (int)t; fr = t - (float)ix;
            gd = gt2[ix]; o.w = fmaf(fr, gd.y, gd.x);
            ob[i] = o;
        }
    }

    if (bid == 0 && tid == 0) g_epoch = ep + 2 * GRID;
}

extern "C" void kernel_launch(void* const* d_in, const int* in_sizes, int n_in,
                              void* d_out, int out_size) {
    const float* x = (const float*)d_in[0];
    float* out = (float*)d_out;
    cudaFuncSetAttribute(fused, cudaFuncAttributeMaxDynamicSharedMemorySize, SMEMB);
    fused<<<GRID, NT, SMEMB>>>(x, out);
}

// round 15
// speedup vs baseline: 2.0636x; 1.1065x over previous
#include <cuda_runtime.h>

#define NBINS   256
#define SUBBINS 2048                  // 8 sub-bins per bin (was 16)
#define APAR    0.07689350249903885f  // (1/255)^2 / (2*0.01^2)
#define GRATIO  0.85745463520f        // exp(-2*APAR)
#define WSINT   6.3919026f            // sqrt(pi/APAR): interior weight sum
#define FEPS    1e-10f
#define NB      4
#define HW      262144
#define NVEC    (HW / 4)
#define GRID    148                   // 1 CTA/SM
#define GPB     37                    // blocks per batch
#define NT      512
#define TAPS    27                    // +-13 bins (table build)
#define TBLN    2048                  // g-table points (1/8 bin)
// smem float offsets: shu u32[2048] (P1) aliases gtab
#define SM_GTAB 0
#define SM_CDP  2048
#define SM_SCN  2336
#define SM_GT2  4096                  // gt2 float2[2048] -> floats [4096,8192)
#define SMEMB   (8192 * 4)            // 32 KB

// persistent scratch (zero-init at load; invariants restored in-kernel)
__device__ unsigned long long g_comb[NB * SUBBINS];   // natural sub-bin order
__device__ float              g_hist[NB * NBINS];
__device__ unsigned int       g_bar;
__device__ unsigned int       g_epoch;

__device__ __forceinline__ void gbar(unsigned target) {
    __syncthreads();
    if (threadIdx.x == 0) {
        __threadfence();
        atomicAdd(&g_bar, 1u);
        unsigned v;
        do {
            asm volatile("ld.global.acquire.gpu.b32 %0, [%1];"
                         : "=r"(v) : "l"(&g_bar) : "memory");
        } while (v < target);
    }
    __syncthreads();
}

__global__ __launch_bounds__(NT, 1) void fused(const float* __restrict__ x,
                                               float* __restrict__ out) {
    extern __shared__ __align__(16) float smf[];
    float*    gtab = smf + SM_GTAB;
    float*    cdp  = smf + SM_CDP;           // zero-padded cdfn
    float*    scn  = smf + SM_SCN;
    float2*   gt2  = (float2*)(smf + SM_GT2);
    unsigned* shu  = (unsigned*)smf;         // P1 alias (dead before P4)

    const int tid   = threadIdx.x;
    const int bid   = blockIdx.x;
    const int lane  = tid & 31;
    const int warp  = tid >> 5;
    const int batch = bid / GPB;
    const int sub   = bid % GPB;

    __shared__ unsigned s_ep;
    if (tid == 0) s_ep = g_epoch;

    // ---- P1: packed sub-bin histogram (smem atomics, natural order) ----
    for (int i = tid; i < SUBBINS; i += NT) shu[i] = 0u;
    __syncthreads();
    const unsigned ep = s_ep;

    const float4* xb = (const float4*)(x + (size_t)batch * HW);
    for (int i = sub * NT + tid; i < NVEC; i += GPB * NT) {
        float4 v = xb[i];
        float vals[4] = {v.x, v.y, v.z, v.w};
        #pragma unroll
        for (int q = 0; q < 4; q++) {
            // p = floor(v*2040*1024); s = p>>10 (<=2039); field = 7680+(p&1023)
            float tk = vals[q] * 2088960.0f;
            unsigned p = (unsigned)tk;
            atomicAdd(&shu[p >> 10], 0x101E00u + (p & 1023u));
        }
    }
    __syncthreads();
    for (int i = tid; i < SUBBINS; i += NT) {
        unsigned v = shu[i];
        if (v) {
            unsigned long long w = ((unsigned long long)(v >> 20) << 48)
                                 | (unsigned long long)(v & 0xFFFFFu);
            atomicAdd(&g_comb[batch * SUBBINS + i], w);
        }
    }
    gbar(ep + GRID);

    // ---- P2: conv -> hist (one warp per bin, distributed over 64 blocks) ----
    {
        int wg = bid * 16 + warp;
        if (wg < NB * NBINS) {
            int b = wg >> 8, j = wg & 255;
            float h = 0.f;
            int sbase = 8 * j - 112 + lane;         // +-14 bins = 224 sub-bins
            #pragma unroll
            for (int t = 0; t < 7; t++) {
                int s = sbase + t * 32;
                if ((unsigned)s < (unsigned)SUBBINS) {
                    unsigned long long cw = __ldcg(&g_comb[b * SUBBINS + s]);
                    float cnt = (float)(unsigned)(cw >> 48);
                    long long df = (long long)(cw & 0xFFFFFFFFFFFFull)
                                 - ((long long)(cw >> 48) << 13);
                    float dev = (float)df * 1.220703125e-4f;   // 2^-13
                    float d = ((float)s + 0.5f) * 0.125f - (float)j;
                    float w = __expf(-APAR * d * d);
                    h = fmaf(cnt, w, h);
                    h = fmaf(dev, -2.0f * APAR * d * w, h);
                }
            }
            #pragma unroll
            for (int o = 16; o; o >>= 1) h += __shfl_xor_sync(0xFFFFFFFFu, h, o);
            if (lane == 0) g_hist[wg] = h;
        }
    }
    gbar(ep + 2 * GRID);

    // ---- P3': every block: zero own g_comb slice; local scan -> cdfn in cdp ----
    {
        const int chunk = (NB * SUBBINS + GRID - 1) / GRID;   // 56
        int base = bid * chunk;
        for (int p = base + tid; p < base + chunk && p < NB * SUBBINS; p += NT)
            g_comb[p] = 0ull;

        if (tid < 288) cdp[tid] = 0.f;       // zero-pad (edges stay 0)
        if (tid < NBINS) scn[tid] = __ldcg(&g_hist[batch * NBINS + tid]);
        __syncthreads();
        for (int off = 1; off < NBINS; off <<= 1) {
            float add = (tid < NBINS && tid >= off) ? scn[tid - off] : 0.f;
            __syncthreads();
            if (tid < NBINS) scn[tid] += add;
            __syncthreads();
        }
        if (tid < NBINS) {
            float S = scn[NBINS - 1];
            float invS = 1.0f / (S + FEPS);
            float c0 = scn[0] * invS;
            cdp[tid + 13] = (scn[tid] * invS - c0) / (1.0f - c0 + FEPS);
        }
        __syncthreads();
    }

    // ---- P4: build 2048-pt g-table, then (value,delta) pairs ----
    {
        #pragma unroll
        for (int it = 0; it < TBLN / NT; it++) {
            int   m  = it * NT + tid;
            int   fl = m >> 3;
            float d0 = (float)(m & 7) * 0.125f + 13.0f;
            float w  = __expf(-APAR * d0 * d0);
            float f  = __expf(fmaf(2.0f * APAR, d0, -APAR));
            const float w0 = w, f0 = f;
            float acc = 0.f;
            #pragma unroll
            for (int k = 0; k < TAPS; k++) {
                acc = fmaf(w, cdp[fl + k], acc);    // zero-padded: no predicate
                w *= f;
                f *= GRATIO;
            }
            float ws;
            if (fl >= 13 && fl <= 242) {
                ws = WSINT;                          // interior: analytic constant
            } else {
                ws = 0.f; w = w0; f = f0;
                #pragma unroll
                for (int k = 0; k < TAPS; k++) {
                    int jj = fl - 13 + k;
                    ws += ((unsigned)jj < 256u) ? w : 0.f;
                    w *= f;
                    f *= GRATIO;
                }
            }
            gtab[m] = __fdividef(acc, ws + FEPS);
        }
        __syncthreads();
        for (int m = tid; m < TBLN; m += NT) {
            float lo = gtab[m];
            float hi = (m < TBLN - 1) ? gtab[m + 1] : lo;
            gt2[m] = make_float2(lo, hi - lo);
        }
        __syncthreads();
    }

    // ---- P5: per-pixel lerp, one LDS.64 + FMA per pixel ----
    {
        float4* ob = (float4*)(out + (size_t)batch * HW);
        for (int i = sub * NT + tid; i < NVEC; i += GPB * NT) {
            float4 v = xb[i];
            float4 o;
            float t; int ix; float fr; float2 gd;
            t = v.x * 2040.0f; ix = (int)t; fr = t - (float)ix;
            gd = gt2[ix]; o.x = fmaf(fr, gd.y, gd.x);
            t = v.y * 2040.0f; ix = (int)t; fr = t - (float)ix;
            gd = gt2[ix]; o.y = fmaf(fr, gd.y, gd.x);
            t = v.z * 2040.0f; ix = (int)t; fr = t - (float)ix;
            gd = gt2[ix]; o.z = fmaf(fr, gd.y, gd.x);
            t = v.w * 2040.0f; ix = (int)t; fr = t - (float)ix;
            gd = gt2[ix]; o.w = fmaf(fr, gd.y, gd.x);
            ob[i] = o;
        }
    }

    if (bid == 0 && tid == 0) g_epoch = ep + 2 * GRID;
}

extern "C" void kernel_launch(void* const* d_in, const int* in_sizes, int n_in,
                              void* d_out, int out_size) {
    const float* x = (const float*)d_in[0];
    float* out = (float*)d_out;
    cudaFuncSetAttribute(fused, cudaFuncAttributeMaxDynamicSharedMemorySize, SMEMB);
    fused<<<GRID, NT, SMEMB>>>(x, out);
}

// round 16
// speedup vs baseline: 2.2303x; 1.0808x over previous
#include <cuda_runtime.h>

#define NBINS   256
#define SUBBINS 1024                  // 4 sub-bins per bin
#define APAR    0.07689350249903885f  // (1/255)^2 / (2*0.01^2)
#define GRATIO  0.85745463520f        // exp(-2*APAR)
#define WSINT   6.3919026f            // sqrt(pi/APAR): interior weight sum
#define FEPS    1e-10f
#define NB      4
#define HW      262144
#define NVEC    (HW / 4)
#define GRID    148                   // 1 CTA/SM
#define GPB     37                    // blocks per batch
#define NT      512
#define TAPS    27                    // +-13 bins (table build)
#define TBLN    2048                  // g-table points (1/8 bin)
// smem float offsets
#define SM_GTAB 0                     // gtab 2048 (aliases shu u32[1024] in P1)
#define SM_CDP  2048                  // cdp 288
#define SM_SCN  2336                  // scn 256
#define SM_CD2  2592                  // cd2 float2[1024] (byte off 10368, 8-aligned)
#define SM_GT2  4640                  // gt2 float2[2048] (byte off 18560, 8-aligned)
#define SMEMB   ((4640 + 4096) * 4)   // 34944 B

// persistent scratch: double-buffered by replay parity (zero-init at load)
__device__ unsigned long long g_comb[2][NB * SUBBINS];
__device__ unsigned int       g_bar;
__device__ unsigned int       g_epoch;

__device__ __forceinline__ void gbar(unsigned target) {
    __syncthreads();
    if (threadIdx.x == 0) {
        __threadfence();
        atomicAdd(&g_bar, 1u);
        unsigned v;
        do {
            asm volatile("ld.global.acquire.gpu.b32 %0, [%1];"
                         : "=r"(v) : "l"(&g_bar) : "memory");
        } while (v < target);
    }
    __syncthreads();
}

__global__ __launch_bounds__(NT, 1) void fused(const float* __restrict__ x,
                                               float* __restrict__ out) {
    extern __shared__ __align__(16) float smf[];
    float*    gtab = smf + SM_GTAB;
    float*    cdp  = smf + SM_CDP;           // zero-padded cdfn
    float*    scn  = smf + SM_SCN;
    float2*   cd2  = (float2*)(smf + SM_CD2);
    float2*   gt2  = (float2*)(smf + SM_GT2);
    unsigned* shu  = (unsigned*)smf;         // P1 alias (dead before P4)

    const int tid   = threadIdx.x;
    const int bid   = blockIdx.x;
    const int lane  = tid & 31;
    const int warp  = tid >> 5;
    const int batch = bid / GPB;
    const int sub   = bid % GPB;

    __shared__ unsigned s_ep;
    if (tid == 0) s_ep = g_epoch;

    // ---- P1: packed sub-bin histogram (smem atomics, natural order) ----
    for (int i = tid; i < SUBBINS; i += NT) shu[i] = 0u;
    __syncthreads();
    const unsigned ep  = s_ep;
    const int      par = (int)((ep / GRID) & 1u);

    const float4* xb = (const float4*)(x + (size_t)batch * HW);
    for (int i = sub * NT + tid; i < NVEC; i += GPB * NT) {
        float4 v = xb[i];
        float vals[4] = {v.x, v.y, v.z, v.w};
        #pragma unroll
        for (int q = 0; q < 4; q++) {
            // p = floor(v*1020*1024); s = p>>10 (<=1019); field = 7680+(p&1023)
            float tk = vals[q] * 1044480.0f;
            unsigned p = (unsigned)tk;
            atomicAdd(&shu[p >> 10], 0x101E00u + (p & 1023u));
        }
    }
    __syncthreads();
    unsigned long long* cbuf = g_comb[par];
    for (int i = tid; i < SUBBINS; i += NT) {
        unsigned v = shu[i];
        if (v) {
            unsigned long long w = ((unsigned long long)(v >> 20) << 48)
                                 | (unsigned long long)(v & 0xFFFFFu);
            atomicAdd(&cbuf[batch * SUBBINS + i], w);
        }
    }
    gbar(ep + GRID);

    // ---- P2': block-local: decode own batch, zero other buffer's slice ----
    {
        const unsigned long long* src = cbuf + batch * SUBBINS;
        for (int i = tid; i < SUBBINS; i += NT) {
            unsigned long long t = __ldcg(&src[i]);
            float cnt = (float)(unsigned)(t >> 48);
            long long df = (long long)(t & 0xFFFFFFFFFFFFull)
                         - ((long long)(t >> 48) << 13);
            cd2[i] = make_float2(cnt, (float)df * 2.44140625e-4f);  // 2^-12
        }
        // zero a slice of the OTHER buffer (no reader this replay)
        unsigned long long* obuf = g_comb[par ^ 1];
        const int chunk = (NB * SUBBINS + GRID - 1) / GRID;        // 28
        int base = bid * chunk;
        for (int p = base + tid; p < base + chunk && p < NB * SUBBINS; p += NT)
            obuf[p] = 0ull;

        if (tid < 288) cdp[tid] = 0.f;       // zero-pad for table build
        __syncthreads();

        // conv: warp w -> bins [16w,16w+16); tap weights are j-independent
        float cw[4], cwd[4];
        #pragma unroll
        for (int t = 0; t < 4; t++) {
            float dd = ((float)(lane + 32 * t) - 63.5f) * 0.25f;   // +-16 bins
            cw[t]  = __expf(-APAR * dd * dd);
            cwd[t] = -2.0f * APAR * dd * cw[t];
        }
        #pragma unroll 1
        for (int bb = 0; bb < 16; bb++) {
            int j = warp * 16 + bb;
            int sbase = 4 * j - 64 + lane;
            float h = 0.f;
            #pragma unroll
            for (int t = 0; t < 4; t++) {
                int s = sbase + 32 * t;
                if ((unsigned)s < (unsigned)SUBBINS) {
                    float2 cd = cd2[s];
                    h = fmaf(cd.x, cw[t], h);
                    h = fmaf(cd.y, cwd[t], h);
                }
            }
            #pragma unroll
            for (int o = 16; o; o >>= 1) h += __shfl_xor_sync(0xFFFFFFFFu, h, o);
            if (lane == 0) scn[j] = h;
        }
        __syncthreads();

        // inclusive scan + normalize -> cdp[13..268]
        for (int off = 1; off < NBINS; off <<= 1) {
            float add = (tid < NBINS && tid >= off) ? scn[tid - off] : 0.f;
            __syncthreads();
            if (tid < NBINS) scn[tid] += add;
            __syncthreads();
        }
        if (tid < NBINS) {
            float S = scn[NBINS - 1];
            float invS = 1.0f / (S + FEPS);
            float c0 = scn[0] * invS;
            cdp[tid + 13] = (scn[tid] * invS - c0) / (1.0f - c0 + FEPS);
        }
        __syncthreads();
    }

    // ---- P4: build 2048-pt g-table, then (value,delta) pairs ----
    {
        #pragma unroll
        for (int it = 0; it < TBLN / NT; it++) {
            int   m  = it * NT + tid;
            int   fl = m >> 3;
            float d0 = (float)(m & 7) * 0.125f + 13.0f;
            float w  = __expf(-APAR * d0 * d0);
            float f  = __expf(fmaf(2.0f * APAR, d0, -APAR));
            const float w0 = w, f0 = f;
            float acc = 0.f;
            #pragma unroll
            for (int k = 0; k < TAPS; k++) {
                acc = fmaf(w, cdp[fl + k], acc);    // zero-padded: no predicate
                w *= f;
                f *= GRATIO;
            }
            float ws;
            if (fl >= 13 && fl <= 242) {
                ws = WSINT;                          // interior: analytic constant
            } else {
                ws = 0.f; w = w0; f = f0;
                #pragma unroll
                for (int k = 0; k < TAPS; k++) {
                    int jj = fl - 13 + k;
                    ws += ((unsigned)jj < 256u) ? w : 0.f;
                    w *= f;
                    f *= GRATIO;
                }
            }
            gtab[m] = __fdividef(acc, ws + FEPS);
        }
        __syncthreads();
        for (int m = tid; m < TBLN; m += NT) {
            float lo = gtab[m];
            float hi = (m < TBLN - 1) ? gtab[m + 1] : lo;
            gt2[m] = make_float2(lo, hi - lo);
        }
        __syncthreads();
    }

    // ---- P5: per-pixel lerp, one LDS.64 + FMA per pixel ----
    {
        float4* ob = (float4*)(out + (size_t)batch * HW);
        for (int i = sub * NT + tid; i < NVEC; i += GPB * NT) {
            float4 v = xb[i];
            float4 o;
            float t; int ix; float fr; float2 gd;
            t = v.x * 2040.0f; ix = (int)t; fr = t - (float)ix;
            gd = gt2[ix]; o.x = fmaf(fr, gd.y, gd.x);
            t = v.y * 2040.0f; ix = (int)t; fr = t - (float)ix;
            gd = gt2[ix]; o.y = fmaf(fr, gd.y, gd.x);
            t = v.z * 2040.0f; ix = (int)t; fr = t - (float)ix;
            gd = gt2[ix]; o.z = fmaf(fr, gd.y, gd.x);
            t = v.w * 2040.0f; ix = (int)t; fr = t - (float)ix;
            gd = gt2[ix]; o.w = fmaf(fr, gd.y, gd.x);
            ob[i] = o;
        }
    }

    if (bid == 0 && tid == 0) g_epoch = ep + GRID;
}

extern "C" void kernel_launch(void* const* d_in, const int* in_sizes, int n_in,
                              void* d_out, int out_size) {
    const float* x = (const float*)d_in[0];
    float* out = (float*)d_out;
    cudaFuncSetAttribute(fused, cudaFuncAttributeMaxDynamicSharedMemorySize, SMEMB);
    fused<<<GRID, NT, SMEMB>>>(x, out);
}

// round 17
// speedup vs baseline: 2.3390x; 1.0487x over previous
#include <cuda_runtime.h>

#define NBINS   256
#define SUBBINS 1024                  // 4 sub-bins per bin
#define APAR    0.07689350249903885f  // (1/255)^2 / (2*0.01^2)
#define GRATIO  0.85745463520f        // exp(-2*APAR)
#define WSINT   6.3919026f            // sqrt(pi/APAR): interior weight sum
#define FEPS    1e-10f
#define NB      4
#define HW      262144
#define NVEC    (HW / 4)
#define GRID    148                   // 1 CTA/SM
#define GPB     37                    // blocks per batch
#define NT      512
#define TAPS    27                    // +-13 bins (table build)
#define TBLN    1024                  // g-table points (1/4 bin)
// smem float offsets
#define SM_GTAB 0                     // gtab 1024 (aliases shu u32[1024] in P1)
#define SM_CDP  1024                  // cdp 288
#define SM_SCN  1312                  // scn 256
#define SM_WSM  1568                  // wsum 16
#define SM_CD2  1584                  // cd2 float2[1152] padded +-64
#define SM_GT2  3888                  // gt2 float2[1024]
#define SMEMB   (5936 * 4)            // 23744 B

// persistent scratch: double-buffered by replay parity (zero-init at load)
__device__ unsigned long long g_comb[2][NB * SUBBINS];
__device__ unsigned int       g_bar;
__device__ unsigned int       g_epoch;

__device__ __forceinline__ void gbar(unsigned target) {
    __syncthreads();
    if (threadIdx.x == 0) {
        __threadfence();
        atomicAdd(&g_bar, 1u);
        unsigned v;
        do {
            asm volatile("ld.global.acquire.gpu.b32 %0, [%1];"
                         : "=r"(v) : "l"(&g_bar) : "memory");
        } while (v < target);
    }
    __syncthreads();
}

__global__ __launch_bounds__(NT, 1) void fused(const float* __restrict__ x,
                                               float* __restrict__ out) {
    extern __shared__ __align__(16) float smf[];
    float*    gtab = smf + SM_GTAB;
    float*    cdp  = smf + SM_CDP;           // zero-padded cdfn
    float*    scn  = smf + SM_SCN;
    float*    wsm  = smf + SM_WSM;
    float2*   cd2  = (float2*)(smf + SM_CD2);  // index i <-> sub-bin s = i-64
    float2*   gt2  = (float2*)(smf + SM_GT2);
    unsigned* shu  = (unsigned*)smf;         // P1 alias (dead before P4)

    const int tid   = threadIdx.x;
    const int bid   = blockIdx.x;
    const int lane  = tid & 31;
    const int warp  = tid >> 5;
    const int batch = bid / GPB;
    const int sub   = bid % GPB;
    // balanced contiguous chunk of this batch's float4s
    const int i0 = (sub * NVEC) / GPB;
    const int i1 = ((sub + 1) * NVEC) / GPB;

    __shared__ unsigned s_ep;
    if (tid == 0) s_ep = g_epoch;

    // ---- P1: packed sub-bin histogram (smem atomics, natural order) ----
    for (int i = tid; i < SUBBINS; i += NT) shu[i] = 0u;
    __syncthreads();
    const unsigned ep  = s_ep;
    const int      par = (int)((ep / GRID) & 1u);

    const float4* xb = (const float4*)(x + (size_t)batch * HW);
    for (int i = i0 + tid; i < i1; i += NT) {
        float4 v = xb[i];
        float vals[4] = {v.x, v.y, v.z, v.w};
        #pragma unroll
        for (int q = 0; q < 4; q++) {
            // p = floor(v*1020*1024); s = p>>10 (<=1019); field = 7680+(p&1023)
            float tk = vals[q] * 1044480.0f;
            unsigned p = (unsigned)tk;
            atomicAdd(&shu[p >> 10], 0x101E00u + (p & 1023u));
        }
    }
    __syncthreads();
    unsigned long long* cbuf = g_comb[par];
    for (int i = tid; i < SUBBINS; i += NT) {
        unsigned v = shu[i];
        if (v) {
            unsigned long long w = ((unsigned long long)(v >> 20) << 48)
                                 | (unsigned long long)(v & 0xFFFFFu);
            atomicAdd(&cbuf[batch * SUBBINS + i], w);
        }
    }
    gbar(ep + GRID);

    // ---- P2': block-local decode (padded), conv, shuffle-scan -> cdfn ----
    {
        const unsigned long long* src = cbuf + batch * SUBBINS;
        for (int i = tid; i < 1152; i += NT) {
            float2 cv = make_float2(0.f, 0.f);
            if (i >= 64 && i < 64 + SUBBINS) {
                unsigned long long t = __ldcg(&src[i - 64]);
                float cnt = (float)(unsigned)(t >> 48);
                long long df = (long long)(t & 0xFFFFFFFFFFFFull)
                             - ((long long)(t >> 48) << 13);
                cv = make_float2(cnt, (float)df * 2.44140625e-4f);  // 2^-12
            }
            cd2[i] = cv;
        }
        if (tid < 288) cdp[tid] = 0.f;       // zero-pad for table build
        __syncthreads();

        // conv: warp w -> bins [16w,16w+16); taps j-independent, pads zero
        float cw[4], cwd[4];
        #pragma unroll
        for (int t = 0; t < 4; t++) {
            float dd = ((float)(lane + 32 * t) - 63.5f) * 0.25f;   // +-16 bins
            cw[t]  = __expf(-APAR * dd * dd);
            cwd[t] = -2.0f * APAR * dd * cw[t];
        }
        #pragma unroll 1
        for (int bb = 0; bb < 16; bb++) {
            int j = warp * 16 + bb;
            int base = 4 * j + lane;          // cd2 idx = s+64 = 4j-64+lane+64
            float h = 0.f;
            #pragma unroll
            for (int t = 0; t < 4; t++) {
                float2 cd = cd2[base + 32 * t];
                h = fmaf(cd.x, cw[t], h);
                h = fmaf(cd.y, cwd[t], h);
            }
            #pragma unroll
            for (int o = 16; o; o >>= 1) h += __shfl_xor_sync(0xFFFFFFFFu, h, o);
            if (lane == 0) scn[j] = h;
        }
        __syncthreads();

        // shuffle-based inclusive scan of scn[0..255] -> cdfn in cdp[13..268]
        float v = (tid < NBINS) ? scn[tid] : 0.f;
        #pragma unroll
        for (int o = 1; o < 32; o <<= 1) {
            float n = __shfl_up_sync(0xFFFFFFFFu, v, o);
            if (lane >= o) v += n;
        }
        if (tid < NBINS && lane == 31) wsm[warp] = v;
        __syncthreads();
        if (tid < NBINS) {
            float off = 0.f, Stot = 0.f;
            #pragma unroll
            for (int k = 0; k < 8; k++) {
                float wk = wsm[k];
                Stot += wk;
                off  += (k < warp) ? wk : 0.f;
            }
            v += off;
            float invS = 1.0f / (Stot + FEPS);
            float c0 = scn[0] * invS;
            cdp[tid + 13] = (v * invS - c0) / (1.0f - c0 + FEPS);
        }
        __syncthreads();
    }

    // ---- P4: build 1024-pt g-table, then (value,delta) pairs ----
    {
        #pragma unroll
        for (int it = 0; it < TBLN / NT; it++) {
            int   m  = it * NT + tid;
            int   fl = m >> 2;
            float d0 = (float)(m & 3) * 0.25f + 13.0f;
            float w  = __expf(-APAR * d0 * d0);
            float f  = __expf(fmaf(2.0f * APAR, d0, -APAR));
            const float w0 = w, f0 = f;
            float acc = 0.f;
            #pragma unroll
            for (int k = 0; k < TAPS; k++) {
                acc = fmaf(w, cdp[fl + k], acc);    // zero-padded: no predicate
                w *= f;
                f *= GRATIO;
            }
            float ws;
            if (fl >= 13 && fl <= 242) {
                ws = WSINT;                          // interior: analytic constant
            } else {
                ws = 0.f; w = w0; f = f0;
                #pragma unroll
                for (int k = 0; k < TAPS; k++) {
                    int jj = fl - 13 + k;
                    ws += ((unsigned)jj < 256u) ? w : 0.f;
                    w *= f;
                    f *= GRATIO;
                }
            }
            gtab[m] = __fdividef(acc, ws + FEPS);
        }
        __syncthreads();
        for (int m = tid; m < TBLN; m += NT) {
            float lo = gtab[m];
            float hi = (m < TBLN - 1) ? gtab[m + 1] : lo;
            gt2[m] = make_float2(lo, hi - lo);
        }
        __syncthreads();
    }

    // ---- P5: per-pixel lerp, one LDS.64 + FMA per pixel ----
    {
        float4* ob = (float4*)(out + (size_t)batch * HW);
        for (int i = i0 + tid; i < i1; i += NT) {
            float4 v = xb[i];
            float4 o;
            float t; int ix; float fr; float2 gd;
            t = v.x * 1020.0f; ix = (int)t; fr = t - (float)ix;
            gd = gt2[ix]; o.x = fmaf(fr, gd.y, gd.x);
            t = v.y * 1020.0f; ix = (int)t; fr = t - (float)ix;
            gd = gt2[ix]; o.y = fmaf(fr, gd.y, gd.x);
            t = v.z * 1020.0f; ix = (int)t; fr = t - (float)ix;
            gd = gt2[ix]; o.z = fmaf(fr, gd.y, gd.x);
            t = v.w * 1020.0f; ix = (int)t; fr = t - (float)ix;
            gd = gt2[ix]; o.w = fmaf(fr, gd.y, gd.x);
            ob[i] = o;
        }
    }

    // ---- off critical path: zero the OTHER buffer's slice for next replay ----
    {
        unsigned long long* obuf = g_comb[par ^ 1];
        const int chunk = (NB * SUBBINS + GRID - 1) / GRID;   // 28
        int base = bid * chunk;
        for (int p = base + tid; p < base + chunk && p < NB * SUBBINS; p += NT)
            obuf[p] = 0ull;
    }

    if (bid == 0 && tid == 0) g_epoch = ep + GRID;
}

extern "C" void kernel_launch(void* const* d_in, const int* in_sizes, int n_in,
                              void* d_out, int out_size) {
    const float* x = (const float*)d_in[0];
    float* out = (float*)d_out;
    cudaFuncSetAttribute(fused, cudaFuncAttributeMaxDynamicSharedMemorySize, SMEMB);
    fused<<<GRID, NT, SMEMB>>>(x, out);
}